// round 1
// baseline (speedup 1.0000x reference)
#include <cuda_runtime.h>
#include <cstdint>
#include <math.h>

// ---------------- problem constants ----------------
#define BS_      16
#define LQ_      1000
#define NROWS    (BS_*LQ_)         // 16000
#define EMBED    256
#define NHEADS   8
#define SUMP     16
#define HDIM     32
#define NLOGIT   384               // 256 offset cols + 128 attn cols
#define LV_      13294

__device__ float g_logits[NROWS * NLOGIT];   // scratch: off(256) | attn(128) per row

// spatial levels (hardcoded per reference)
__device__ __constant__ int d_dummy; // (none needed; constants folded below)

// ---------------- Kernel A: fused SGEMM  C[16000,384] = Q[16000,256] @ [W_off|W_attn] + bias ----------------
#define BM 128
#define BN 128
#define BKK 8
#define TM 8
#define TN 8

__global__ __launch_bounds__(256, 2)
void gemm_kernel(const float* __restrict__ Q,
                 const float* __restrict__ Woff,
                 const float* __restrict__ Wattn,
                 const float* __restrict__ boff,
                 const float* __restrict__ battn)
{
    __shared__ float As[BKK][BM];
    __shared__ float Bs[BKK][BN];

    const int bm = blockIdx.x;           // 0..124
    const int bn = blockIdx.y;           // 0..2

    const float* Bsrc;
    int ldb;
    const float* bias;
    if (bn < 2) { Bsrc = Woff + bn * 128; ldb = 256; bias = boff + bn * 128; }
    else        { Bsrc = Wattn;           ldb = 128; bias = battn; }

    const float* A = Q + (size_t)bm * BM * EMBED;

    const int tid  = threadIdx.x;
    const int tcol = tid & 15;           // 0..15 (BN/TN)
    const int trow = tid >> 4;           // 0..15 (BM/TM)

    const int arow = tid >> 1;           // 0..127
    const int acol = (tid & 1) * 4;      // 0 or 4
    const int brow = tid >> 5;           // 0..7
    const int bcol = (tid & 31) * 4;     // 0..124

    float acc[TM][TN];
    #pragma unroll
    for (int i = 0; i < TM; i++)
        #pragma unroll
        for (int j = 0; j < TN; j++) acc[i][j] = 0.f;

    for (int k0 = 0; k0 < EMBED; k0 += BKK) {
        float4 av = *reinterpret_cast<const float4*>(A + (size_t)arow * EMBED + k0 + acol);
        As[acol + 0][arow] = av.x;
        As[acol + 1][arow] = av.y;
        As[acol + 2][arow] = av.z;
        As[acol + 3][arow] = av.w;
        float4 bv = *reinterpret_cast<const float4*>(Bsrc + (size_t)(k0 + brow) * ldb + bcol);
        *reinterpret_cast<float4*>(&Bs[brow][bcol]) = bv;
        __syncthreads();

        #pragma unroll
        for (int kk = 0; kk < BKK; kk++) {
            float4 a0 = *reinterpret_cast<const float4*>(&As[kk][trow * TM]);
            float4 a1 = *reinterpret_cast<const float4*>(&As[kk][trow * TM + 4]);
            float4 b0 = *reinterpret_cast<const float4*>(&Bs[kk][tcol * TN]);
            float4 b1 = *reinterpret_cast<const float4*>(&Bs[kk][tcol * TN + 4]);
            float ar[TM] = {a0.x, a0.y, a0.z, a0.w, a1.x, a1.y, a1.z, a1.w};
            float br[TN] = {b0.x, b0.y, b0.z, b0.w, b1.x, b1.y, b1.z, b1.w};
            #pragma unroll
            for (int i = 0; i < TM; i++)
                #pragma unroll
                for (int j = 0; j < TN; j++)
                    acc[i][j] = fmaf(ar[i], br[j], acc[i][j]);
        }
        __syncthreads();
    }

    // epilogue: + bias, write to g_logits
    float bv[TN];
    #pragma unroll
    for (int j = 0; j < TN; j++) bv[j] = bias[tcol * TN + j];

    #pragma unroll
    for (int i = 0; i < TM; i++) {
        int row = bm * BM + trow * TM + i;
        float* op = g_logits + (size_t)row * NLOGIT + bn * 128 + tcol * TN;
        float4 o0, o1;
        o0.x = acc[i][0] + bv[0]; o0.y = acc[i][1] + bv[1];
        o0.z = acc[i][2] + bv[2]; o0.w = acc[i][3] + bv[3];
        o1.x = acc[i][4] + bv[4]; o1.y = acc[i][5] + bv[5];
        o1.z = acc[i][6] + bv[6]; o1.w = acc[i][7] + bv[7];
        *reinterpret_cast<float4*>(op)     = o0;
        *reinterpret_cast<float4*>(op + 4) = o1;
    }
}

// ---------------- Kernel B: softmax + bilinear sampling ----------------
// one warp per (b, h, q); lane = head-dim for the gather phase.
// lanes 0..15 carry per-point x data, lanes 16..31 per-point y data.

__global__ __launch_bounds__(256)
void sample_kernel(const float* __restrict__ value,
                   const float* __restrict__ refp,
                   float* __restrict__ out)
{
    constexpr int cW[4]  = {100, 50, 25, 13};
    constexpr int cH[4]  = {100, 50, 25, 13};
    constexpr int cVS[4] = {0, 10000, 12500, 13125};

    const int warp = (blockIdx.x << 3) + (threadIdx.x >> 5);   // 0..127999
    const int lane = threadIdx.x & 31;

    const int q  = warp % LQ_;
    const int bh = warp / LQ_;
    const int b  = bh >> 3;
    const int h  = bh & 7;
    const int row = b * LQ_ + q;

    const float* lg = g_logits + (size_t)row * NLOGIT;
    const float4 rp = __ldg(reinterpret_cast<const float4*>(refp) + row);

    const int  p2  = lane & 15;
    const bool isY = lane >= 16;

    // ---- softmax over 16 attn logits (lanes 0..15 hold them) ----
    float logit = (lane < 16) ? __ldg(lg + 256 + h * 16 + lane) : -INFINITY;
    float m = logit;
    #pragma unroll
    for (int o = 16; o; o >>= 1) m = fmaxf(m, __shfl_xor_sync(0xffffffffu, m, o));
    float e = (lane < 16) ? __expf(logit - m) : 0.f;
    float s = e;
    #pragma unroll
    for (int o = 16; o; o >>= 1) s += __shfl_xor_sync(0xffffffffu, s, o);
    const float a = e / s;

    // ---- per-point coordinate (x in lanes 0..15, y in lanes 16..31) ----
    const float off = __ldg(lg + ((h * 16 + p2) << 1) + (isY ? 1 : 0));
    const int lvl = p2 >> 2;
    const float dim = (float)(isY ? cH[lvl] : cW[lvl]);
    const float rc  = isY ? rp.y : rp.x;
    const float rs  = isY ? rp.w : rp.z;
    // pos = (rc + off * 0.25 * rs * 0.5) * dim - 0.5
    const float pos = fmaf(fmaf(off, 0.125f * rs, rc), dim, -0.5f);
    const float f0  = floorf(pos);
    const float fr  = pos - f0;
    const int   i0  = (int)f0;

    const float* vb = value + (size_t)b * LV_ * EMBED + h * HDIM + lane;

    float acc = 0.f;
    #pragma unroll
    for (int p = 0; p < SUMP; p++) {
        const int l  = p >> 2;
        const int W  = cW[l];
        const int H  = cH[l];
        const int VS = cVS[l];

        const int   x0 = __shfl_sync(0xffffffffu, i0, p);
        const int   y0 = __shfl_sync(0xffffffffu, i0, p + 16);
        const float fx = __shfl_sync(0xffffffffu, fr, p);
        const float fy = __shfl_sync(0xffffffffu, fr, p + 16);
        const float ap = __shfl_sync(0xffffffffu, a,  p);

        const float gx = 1.f - fx, gy = 1.f - fy;

        const bool xin0 = (x0 >= 0)  && (x0 < W);
        const bool xin1 = (x0 >= -1) && (x0 < W - 1);
        const bool yin0 = (y0 >= 0)  && (y0 < H);
        const bool yin1 = (y0 >= -1) && (y0 < H - 1);

        const float* vl = vb + (size_t)VS * EMBED;
        const int base0 = (y0 * W + x0) * EMBED;

        float v00 = 0.f, v10 = 0.f, v01 = 0.f, v11 = 0.f;
        if (xin0 && yin0) v00 = __ldg(vl + base0);
        if (xin1 && yin0) v10 = __ldg(vl + base0 + EMBED);
        if (xin0 && yin1) v01 = __ldg(vl + base0 + W * EMBED);
        if (xin1 && yin1) v11 = __ldg(vl + base0 + W * EMBED + EMBED);

        float sv = fmaf(gx * gy, v00,
                   fmaf(fx * gy, v10,
                   fmaf(gx * fy, v01, (fx * fy) * v11)));
        acc = fmaf(ap, sv, acc);
    }

    out[(size_t)row * EMBED + h * HDIM + lane] = acc;
}

// ---------------- launch ----------------
extern "C" void kernel_launch(void* const* d_in, const int* in_sizes, int n_in,
                              void* d_out, int out_size)
{
    const float* query = (const float*)d_in[0];
    const float* refp  = (const float*)d_in[1];
    const float* value = (const float*)d_in[2];
    // d_in[3] = value_spatial_shapes (int64) — hardcoded
    const float* Woff  = (const float*)d_in[4];
    const float* boff  = (const float*)d_in[5];
    const float* Wattn = (const float*)d_in[6];
    const float* battn = (const float*)d_in[7];
    float* out = (float*)d_out;

    dim3 g(NROWS / BM, NLOGIT / BN);   // (125, 3)
    gemm_kernel<<<g, 256>>>(query, Woff, Wattn, boff, battn);

    sample_kernel<<<(BS_ * NHEADS * LQ_) / 8, 256>>>(value, refp, out);
}

// round 2
// speedup vs baseline: 1.1840x; 1.1840x over previous
#include <cuda_runtime.h>
#include <cstdint>
#include <math.h>

// ---------------- problem constants ----------------
#define BS_      16
#define LQ_      1000
#define NROWS    (BS_*LQ_)         // 16000
#define EMBED    256
#define NHEADS   8
#define SUMP     16
#define HDIM     32
#define NLOGIT   384               // 256 offset cols + 128 attn cols
#define LV_      13294

__device__ float g_logits[NROWS * NLOGIT];   // scratch: off(256) | attn(128) per row

// ---------------- Kernel A: fused SGEMM  C[16000,384] = Q[16000,256] @ [W_off|W_attn] + bias ----------------
#define BM 128
#define BN 128
#define BKK 8
#define TM 8
#define TN 8

__global__ __launch_bounds__(256, 2)
void gemm_kernel(const float* __restrict__ Q,
                 const float* __restrict__ Woff,
                 const float* __restrict__ Wattn,
                 const float* __restrict__ boff,
                 const float* __restrict__ battn)
{
    __shared__ float As[BKK][BM];
    __shared__ float Bs[BKK][BN];

    const int bm = blockIdx.x;           // 0..124
    const int bn = blockIdx.y;           // 0..2

    const float* Bsrc;
    int ldb;
    const float* bias;
    if (bn < 2) { Bsrc = Woff + bn * 128; ldb = 256; bias = boff + bn * 128; }
    else        { Bsrc = Wattn;           ldb = 128; bias = battn; }

    const float* A = Q + (size_t)bm * BM * EMBED;

    const int tid  = threadIdx.x;
    const int tcol = tid & 15;           // 0..15 (BN/TN)
    const int trow = tid >> 4;           // 0..15 (BM/TM)

    const int arow = tid >> 1;           // 0..127
    const int acol = (tid & 1) * 4;      // 0 or 4
    const int brow = tid >> 5;           // 0..7
    const int bcol = (tid & 31) * 4;     // 0..124

    float acc[TM][TN];
    #pragma unroll
    for (int i = 0; i < TM; i++)
        #pragma unroll
        for (int j = 0; j < TN; j++) acc[i][j] = 0.f;

    for (int k0 = 0; k0 < EMBED; k0 += BKK) {
        float4 av = *reinterpret_cast<const float4*>(A + (size_t)arow * EMBED + k0 + acol);
        As[acol + 0][arow] = av.x;
        As[acol + 1][arow] = av.y;
        As[acol + 2][arow] = av.z;
        As[acol + 3][arow] = av.w;
        float4 bv = *reinterpret_cast<const float4*>(Bsrc + (size_t)(k0 + brow) * ldb + bcol);
        *reinterpret_cast<float4*>(&Bs[brow][bcol]) = bv;
        __syncthreads();

        #pragma unroll
        for (int kk = 0; kk < BKK; kk++) {
            float4 a0 = *reinterpret_cast<const float4*>(&As[kk][trow * TM]);
            float4 a1 = *reinterpret_cast<const float4*>(&As[kk][trow * TM + 4]);
            float4 b0 = *reinterpret_cast<const float4*>(&Bs[kk][tcol * TN]);
            float4 b1 = *reinterpret_cast<const float4*>(&Bs[kk][tcol * TN + 4]);
            float ar[TM] = {a0.x, a0.y, a0.z, a0.w, a1.x, a1.y, a1.z, a1.w};
            float br[TN] = {b0.x, b0.y, b0.z, b0.w, b1.x, b1.y, b1.z, b1.w};
            #pragma unroll
            for (int i = 0; i < TM; i++)
                #pragma unroll
                for (int j = 0; j < TN; j++)
                    acc[i][j] = fmaf(ar[i], br[j], acc[i][j]);
        }
        __syncthreads();
    }

    float bv[TN];
    #pragma unroll
    for (int j = 0; j < TN; j++) bv[j] = bias[tcol * TN + j];

    #pragma unroll
    for (int i = 0; i < TM; i++) {
        int row = bm * BM + trow * TM + i;
        float* op = g_logits + (size_t)row * NLOGIT + bn * 128 + tcol * TN;
        float4 o0, o1;
        o0.x = acc[i][0] + bv[0]; o0.y = acc[i][1] + bv[1];
        o0.z = acc[i][2] + bv[2]; o0.w = acc[i][3] + bv[3];
        o1.x = acc[i][4] + bv[4]; o1.y = acc[i][5] + bv[5];
        o1.z = acc[i][6] + bv[6]; o1.w = acc[i][7] + bv[7];
        *reinterpret_cast<float4*>(op)     = o0;
        *reinterpret_cast<float4*>(op + 4) = o1;
    }
}

// ---------------- Kernel B: softmax + bilinear sampling (4-point / float4 vectorized) ----------------
// one warp per (b, h, q).
// Coordinate phase: lanes 0..15 hold x data for point p=lane, lanes 16..31 y data for p=lane-16.
// Gather phase: psub = lane>>3 selects one of 4 points (same level), dgrp = lane&7 covers
// the 32-dim head with float4 loads. Epilogue reduces over psub via xor-shuffles.

__global__ __launch_bounds__(256)
void sample_kernel(const float* __restrict__ value,
                   const float* __restrict__ refp,
                   float* __restrict__ out)
{
    constexpr int cW[4]  = {100, 50, 25, 13};
    constexpr int cVS[4] = {0, 10000, 12500, 13125};

    const int warp = (blockIdx.x << 3) + (threadIdx.x >> 5);   // 0..127999
    const int lane = threadIdx.x & 31;

    const int q  = warp % LQ_;
    const int bh = warp / LQ_;
    const int b  = bh >> 3;
    const int h  = bh & 7;
    const int row = b * LQ_ + q;

    const float* lg = g_logits + (size_t)row * NLOGIT;
    const float4 rp = __ldg(reinterpret_cast<const float4*>(refp) + row);

    const int  p2  = lane & 15;
    const bool isY = lane >= 16;

    // ---- softmax over 16 attn logits (lanes 0..15 hold them) ----
    float logit = (lane < 16) ? __ldg(lg + 256 + h * 16 + lane) : -INFINITY;
    float m = logit;
    #pragma unroll
    for (int o = 16; o; o >>= 1) m = fmaxf(m, __shfl_xor_sync(0xffffffffu, m, o));
    float e = (lane < 16) ? __expf(logit - m) : 0.f;
    float s = e;
    #pragma unroll
    for (int o = 16; o; o >>= 1) s += __shfl_xor_sync(0xffffffffu, s, o);
    const float a = e / s;

    // ---- per-point coordinate (x in lanes 0..15, y in lanes 16..31) ----
    const float off = __ldg(lg + ((h * 16 + p2) << 1) + (isY ? 1 : 0));
    const int lvl = p2 >> 2;
    const float dim = (float)cW[lvl];              // square levels: H == W
    const float rc  = isY ? rp.y : rp.x;
    const float rs  = isY ? rp.w : rp.z;
    // pos = (rc + off * (1/P) * rs * OFFSET_SCALE) * dim - 0.5 ;  (1/4)*(0.5) = 0.125
    const float pos = fmaf(fmaf(off, 0.125f * rs, rc), dim, -0.5f);
    const float f0  = floorf(pos);
    const float fr  = pos - f0;
    const int   i0  = (int)f0;

    // ---- gather phase: 4 points in parallel, float4 per lane ----
    const int psub = lane >> 3;     // 0..3 : which point within the level
    const int dgrp = lane & 7;      // 0..7 : which float4 of the 32-dim head

    const float* vb = value + (size_t)b * LV_ * EMBED + h * HDIM + dgrp * 4;

    float4 acc = make_float4(0.f, 0.f, 0.f, 0.f);

    #pragma unroll
    for (int it = 0; it < 4; it++) {
        const int W  = cW[it];
        const int VS = cVS[it];
        const int p  = (it << 2) + psub;

        const int   x0 = __shfl_sync(0xffffffffu, i0, p);
        const int   y0 = __shfl_sync(0xffffffffu, i0, p + 16);
        const float fx = __shfl_sync(0xffffffffu, fr, p);
        const float fy = __shfl_sync(0xffffffffu, fr, p + 16);
        const float ap = __shfl_sync(0xffffffffu, a,  p);

        const float gx = 1.f - fx, gy = 1.f - fy;
        const float w00 = ap * gx * gy;
        const float w10 = ap * fx * gy;
        const float w01 = ap * gx * fy;
        const float w11 = ap * fx * fy;

        const bool xin0 = (unsigned)x0       < (unsigned)W;
        const bool xin1 = (unsigned)(x0 + 1) < (unsigned)W;
        const bool yin0 = (unsigned)y0       < (unsigned)W;   // H == W
        const bool yin1 = (unsigned)(y0 + 1) < (unsigned)W;

        const float* vl = vb + (size_t)VS * EMBED + (ptrdiff_t)(y0 * W + x0) * EMBED;

        float4 v00 = make_float4(0.f,0.f,0.f,0.f);
        float4 v10 = v00, v01 = v00, v11 = v00;
        if (xin0 && yin0) v00 = *reinterpret_cast<const float4*>(vl);
        if (xin1 && yin0) v10 = *reinterpret_cast<const float4*>(vl + EMBED);
        if (xin0 && yin1) v01 = *reinterpret_cast<const float4*>(vl + W * EMBED);
        if (xin1 && yin1) v11 = *reinterpret_cast<const float4*>(vl + W * EMBED + EMBED);

        acc.x = fmaf(w00, v00.x, fmaf(w10, v10.x, fmaf(w01, v01.x, fmaf(w11, v11.x, acc.x))));
        acc.y = fmaf(w00, v00.y, fmaf(w10, v10.y, fmaf(w01, v01.y, fmaf(w11, v11.y, acc.y))));
        acc.z = fmaf(w00, v00.z, fmaf(w10, v10.z, fmaf(w01, v01.z, fmaf(w11, v11.z, acc.z))));
        acc.w = fmaf(w00, v00.w, fmaf(w10, v10.w, fmaf(w01, v01.w, fmaf(w11, v11.w, acc.w))));
    }

    // ---- reduce over the 4 point-slots (lanes xor 8 and 16) ----
    #pragma unroll
    for (int o = 8; o <= 16; o <<= 1) {
        acc.x += __shfl_xor_sync(0xffffffffu, acc.x, o);
        acc.y += __shfl_xor_sync(0xffffffffu, acc.y, o);
        acc.z += __shfl_xor_sync(0xffffffffu, acc.z, o);
        acc.w += __shfl_xor_sync(0xffffffffu, acc.w, o);
    }

    if (psub == 0) {
        *reinterpret_cast<float4*>(out + (size_t)row * EMBED + h * HDIM + dgrp * 4) = acc;
    }
}

// ---------------- launch ----------------
extern "C" void kernel_launch(void* const* d_in, const int* in_sizes, int n_in,
                              void* d_out, int out_size)
{
    const float* query = (const float*)d_in[0];
    const float* refp  = (const float*)d_in[1];
    const float* value = (const float*)d_in[2];
    // d_in[3] = value_spatial_shapes (int64) — hardcoded
    const float* Woff  = (const float*)d_in[4];
    const float* boff  = (const float*)d_in[5];
    const float* Wattn = (const float*)d_in[6];
    const float* battn = (const float*)d_in[7];
    float* out = (float*)d_out;

    dim3 g(NROWS / BM, NLOGIT / BN);   // (125, 3)
    gemm_kernel<<<g, 256>>>(query, Woff, Wattn, boff, battn);

    sample_kernel<<<(BS_ * NHEADS * LQ_) / 8, 256>>>(value, refp, out);
}

// round 3
// speedup vs baseline: 1.3305x; 1.1238x over previous
#include <cuda_runtime.h>
#include <cstdint>
#include <math.h>

// ---------------- problem constants ----------------
#define BS_      16
#define LQ_      1000
#define NROWS    (BS_*LQ_)         // 16000
#define EMBED    256
#define NHEADS   8
#define SUMP     16
#define HDIM     32
#define NLOGIT   384               // 256 offset cols + 128 attn cols
#define LV_      13294

__device__ float g_logits[NROWS * NLOGIT];   // scratch: off(256) | attn(128) per row

// ---------------- Kernel A: fused SGEMM  C[16000,384] = Q[16000,256] @ [W_off|W_attn] + bias ----------------
// BM=64 x BN=128 tiles, 128 threads, TM=TN=8. grid = (250, 3) = 750 CTAs
// (fine-grained to avoid the 2-wave quantization tail seen with 128x128 tiles).
#define BM 64
#define BN 128
#define BKK 8
#define TM 8
#define TN 8

__global__ __launch_bounds__(128, 5)
void gemm_kernel(const float* __restrict__ Q,
                 const float* __restrict__ Woff,
                 const float* __restrict__ Wattn,
                 const float* __restrict__ boff,
                 const float* __restrict__ battn)
{
    __shared__ float As[BKK][BM];
    __shared__ float Bs[BKK][BN];

    const int bm = blockIdx.x;           // 0..249
    const int bn = blockIdx.y;           // 0..2

    const float* Bsrc;
    int ldb;
    const float* bias;
    if (bn < 2) { Bsrc = Woff + bn * 128; ldb = 256; bias = boff + bn * 128; }
    else        { Bsrc = Wattn;           ldb = 128; bias = battn; }

    const float* A = Q + (size_t)bm * BM * EMBED;

    const int tid  = threadIdx.x;        // 0..127
    const int tcol = tid & 15;           // 0..15 (BN/TN)
    const int trow = tid >> 4;           // 0..7  (BM/TM)

    const int arow = tid >> 1;           // 0..63
    const int acol = (tid & 1) * 4;      // 0 or 4
    const int brow = tid >> 4;           // 0..7
    const int bcol = (tid & 15) * 4;     // 0..60 (two float4 per thread: +0, +64)

    float acc[TM][TN];
    #pragma unroll
    for (int i = 0; i < TM; i++)
        #pragma unroll
        for (int j = 0; j < TN; j++) acc[i][j] = 0.f;

    for (int k0 = 0; k0 < EMBED; k0 += BKK) {
        float4 av = *reinterpret_cast<const float4*>(A + (size_t)arow * EMBED + k0 + acol);
        As[acol + 0][arow] = av.x;
        As[acol + 1][arow] = av.y;
        As[acol + 2][arow] = av.z;
        As[acol + 3][arow] = av.w;
        float4 bv0 = *reinterpret_cast<const float4*>(Bsrc + (size_t)(k0 + brow) * ldb + bcol);
        float4 bv1 = *reinterpret_cast<const float4*>(Bsrc + (size_t)(k0 + brow) * ldb + bcol + 64);
        *reinterpret_cast<float4*>(&Bs[brow][bcol])      = bv0;
        *reinterpret_cast<float4*>(&Bs[brow][bcol + 64]) = bv1;
        __syncthreads();

        #pragma unroll
        for (int kk = 0; kk < BKK; kk++) {
            float4 a0 = *reinterpret_cast<const float4*>(&As[kk][trow * TM]);
            float4 a1 = *reinterpret_cast<const float4*>(&As[kk][trow * TM + 4]);
            float4 b0 = *reinterpret_cast<const float4*>(&Bs[kk][tcol * TN]);
            float4 b1 = *reinterpret_cast<const float4*>(&Bs[kk][tcol * TN + 4]);
            float ar[TM] = {a0.x, a0.y, a0.z, a0.w, a1.x, a1.y, a1.z, a1.w};
            float br[TN] = {b0.x, b0.y, b0.z, b0.w, b1.x, b1.y, b1.z, b1.w};
            #pragma unroll
            for (int i = 0; i < TM; i++)
                #pragma unroll
                for (int j = 0; j < TN; j++)
                    acc[i][j] = fmaf(ar[i], br[j], acc[i][j]);
        }
        __syncthreads();
    }

    float bv[TN];
    #pragma unroll
    for (int j = 0; j < TN; j++) bv[j] = bias[tcol * TN + j];

    #pragma unroll
    for (int i = 0; i < TM; i++) {
        int row = bm * BM + trow * TM + i;
        float* op = g_logits + (size_t)row * NLOGIT + bn * 128 + tcol * TN;
        float4 o0, o1;
        o0.x = acc[i][0] + bv[0]; o0.y = acc[i][1] + bv[1];
        o0.z = acc[i][2] + bv[2]; o0.w = acc[i][3] + bv[3];
        o1.x = acc[i][4] + bv[4]; o1.y = acc[i][5] + bv[5];
        o1.z = acc[i][6] + bv[6]; o1.w = acc[i][7] + bv[7];
        *reinterpret_cast<float4*>(op)     = o0;
        *reinterpret_cast<float4*>(op + 4) = o1;
    }
}

// ---------------- Kernel B: softmax + bilinear sampling (4-point / float4 vectorized) ----------------
// one warp per (b, h, q). Reg-capped to 32 for full occupancy (issue-limited kernel).

__global__ __launch_bounds__(256, 8)
void sample_kernel(const float* __restrict__ value,
                   const float* __restrict__ refp,
                   float* __restrict__ out)
{
    constexpr int cW[4]  = {100, 50, 25, 13};
    constexpr int cVS[4] = {0, 10000, 12500, 13125};

    const int warp = (blockIdx.x << 3) + (threadIdx.x >> 5);   // 0..127999
    const int lane = threadIdx.x & 31;

    const int q  = warp % LQ_;
    const int bh = warp / LQ_;
    const int b  = bh >> 3;
    const int h  = bh & 7;
    const int row = b * LQ_ + q;

    const float* lg = g_logits + (size_t)row * NLOGIT;
    const float4 rp = __ldg(reinterpret_cast<const float4*>(refp) + row);

    const int  p2  = lane & 15;
    const bool isY = lane >= 16;

    // ---- softmax over 16 attn logits (lanes 0..15 hold them) ----
    float logit = (lane < 16) ? __ldg(lg + 256 + h * 16 + lane) : -INFINITY;
    float m = logit;
    #pragma unroll
    for (int o = 16; o; o >>= 1) m = fmaxf(m, __shfl_xor_sync(0xffffffffu, m, o));
    float e = (lane < 16) ? __expf(logit - m) : 0.f;
    float s = e;
    #pragma unroll
    for (int o = 16; o; o >>= 1) s += __shfl_xor_sync(0xffffffffu, s, o);
    const float a = e / s;

    // ---- per-point coordinate (x in lanes 0..15, y in lanes 16..31) ----
    const float off = __ldg(lg + ((h * 16 + p2) << 1) + (isY ? 1 : 0));
    const int lvl = p2 >> 2;
    const float dim = (float)cW[lvl];              // square levels: H == W
    const float rc  = isY ? rp.y : rp.x;
    const float rs  = isY ? rp.w : rp.z;
    // pos = (rc + off * (1/P) * rs * OFFSET_SCALE) * dim - 0.5 ;  (1/4)*(0.5) = 0.125
    const float pos = fmaf(fmaf(off, 0.125f * rs, rc), dim, -0.5f);
    const float f0  = floorf(pos);
    const float fr  = pos - f0;
    const int   i0  = (int)f0;

    // ---- gather phase: 4 points in parallel, float4 per lane ----
    const int psub = lane >> 3;     // 0..3 : which point within the level
    const int dgrp = lane & 7;      // 0..7 : which float4 of the 32-dim head

    const float* vb = value + (size_t)b * LV_ * EMBED + h * HDIM + dgrp * 4;

    float4 acc = make_float4(0.f, 0.f, 0.f, 0.f);

    #pragma unroll
    for (int it = 0; it < 4; it++) {
        const int W  = cW[it];
        const int VS = cVS[it];
        const int p  = (it << 2) + psub;

        const int   x0 = __shfl_sync(0xffffffffu, i0, p);
        const int   y0 = __shfl_sync(0xffffffffu, i0, p + 16);
        const float fx = __shfl_sync(0xffffffffu, fr, p);
        const float fy = __shfl_sync(0xffffffffu, fr, p + 16);
        const float ap = __shfl_sync(0xffffffffu, a,  p);

        const float gx = 1.f - fx, gy = 1.f - fy;
        const float w00 = ap * gx * gy;
        const float w10 = ap * fx * gy;
        const float w01 = ap * gx * fy;
        const float w11 = ap * fx * fy;

        const bool xin0 = (unsigned)x0       < (unsigned)W;
        const bool xin1 = (unsigned)(x0 + 1) < (unsigned)W;
        const bool yin0 = (unsigned)y0       < (unsigned)W;   // H == W
        const bool yin1 = (unsigned)(y0 + 1) < (unsigned)W;

        const float* vl = vb + (size_t)VS * EMBED + (ptrdiff_t)(y0 * W + x0) * EMBED;

        float4 v00 = make_float4(0.f,0.f,0.f,0.f);
        float4 v10 = v00, v01 = v00, v11 = v00;
        if (xin0 && yin0) v00 = *reinterpret_cast<const float4*>(vl);
        if (xin1 && yin0) v10 = *reinterpret_cast<const float4*>(vl + EMBED);
        if (xin0 && yin1) v01 = *reinterpret_cast<const float4*>(vl + W * EMBED);
        if (xin1 && yin1) v11 = *reinterpret_cast<const float4*>(vl + W * EMBED + EMBED);

        acc.x = fmaf(w00, v00.x, fmaf(w10, v10.x, fmaf(w01, v01.x, fmaf(w11, v11.x, acc.x))));
        acc.y = fmaf(w00, v00.y, fmaf(w10, v10.y, fmaf(w01, v01.y, fmaf(w11, v11.y, acc.y))));
        acc.z = fmaf(w00, v00.z, fmaf(w10, v10.z, fmaf(w01, v01.z, fmaf(w11, v11.z, acc.z))));
        acc.w = fmaf(w00, v00.w, fmaf(w10, v10.w, fmaf(w01, v01.w, fmaf(w11, v11.w, acc.w))));
    }

    // ---- reduce over the 4 point-slots (lanes xor 8 and 16) ----
    #pragma unroll
    for (int o = 8; o <= 16; o <<= 1) {
        acc.x += __shfl_xor_sync(0xffffffffu, acc.x, o);
        acc.y += __shfl_xor_sync(0xffffffffu, acc.y, o);
        acc.z += __shfl_xor_sync(0xffffffffu, acc.z, o);
        acc.w += __shfl_xor_sync(0xffffffffu, acc.w, o);
    }

    if (psub == 0) {
        *reinterpret_cast<float4*>(out + (size_t)row * EMBED + h * HDIM + dgrp * 4) = acc;
    }
}

// ---------------- launch ----------------
extern "C" void kernel_launch(void* const* d_in, const int* in_sizes, int n_in,
                              void* d_out, int out_size)
{
    const float* query = (const float*)d_in[0];
    const float* refp  = (const float*)d_in[1];
    const float* value = (const float*)d_in[2];
    // d_in[3] = value_spatial_shapes (int64) — hardcoded
    const float* Woff  = (const float*)d_in[4];
    const float* boff  = (const float*)d_in[5];
    const float* Wattn = (const float*)d_in[6];
    const float* battn = (const float*)d_in[7];
    float* out = (float*)d_out;

    dim3 g(NROWS / BM, NLOGIT / BN);   // (250, 3)
    gemm_kernel<<<g, 128>>>(query, Woff, Wattn, boff, battn);

    sample_kernel<<<(BS_ * NHEADS * LQ_) / 8, 256>>>(value, refp, out);
}